// round 1
// baseline (speedup 1.0000x reference)
#include <cuda_runtime.h>
#include <cuda_bf16.h>
#include <math.h>

// Problem dims (hardcoded from reference)
#define Bb 2
#define Tt 4096
#define Dd 1024
#define Hh 8
#define Kk 128          // head_k_dim
#define Vv 256          // head_v_dim
#define HK (Hh*Kk)      // 1024
#define HV (Hh*Vv)      // 2048
#define BT (Bb*Tt)      // 8192

// ---------------- scratch (static device globals; no allocation) ----------------
__device__ float g_qproj[BT*HK];
__device__ float g_kproj[BT*HK];
__device__ float g_vproj[BT*HV];
__device__ float g_qn[BT*HK];
__device__ float g_kn[BT*HK];
__device__ float g_vn[BT*HV];
__device__ float g_braw[BT*Hh];
__device__ float g_araw[BT*Hh];
__device__ float g_beta[BT*Hh];
__device__ float g_gd[BT*Hh];
__device__ float g_o[BT*HV];
__device__ float g_on[BT*HV];

// ---------------- fp32 tiled GEMM: C[M,N] = A[M,Kd] * B[Kd,N] ----------------
// 128x128 block tile, BK=16, 256 threads, 8x8 microtile.
__global__ __launch_bounds__(256, 2) void sgemm_kernel(
    const float* __restrict__ A, const float* __restrict__ Bm,
    float* __restrict__ C, int M, int N, int Kd)
{
    __shared__ float As[16][128];
    __shared__ float Bs[16][128];
    const int tid  = threadIdx.x;
    const int m0   = blockIdx.y * 128;
    const int n0   = blockIdx.x * 128;
    const int trow = (tid >> 4) << 3;   // 0..120
    const int tcol = (tid & 15) << 3;   // 0..120

    float acc[8][8];
    #pragma unroll
    for (int i = 0; i < 8; i++)
        #pragma unroll
        for (int j = 0; j < 8; j++) acc[i][j] = 0.f;

    for (int k0 = 0; k0 < Kd; k0 += 16) {
        #pragma unroll
        for (int i = 0; i < 2; i++) {
            int idx = tid + i * 256;
            // A: 128 rows x 16 cols, as 512 float4
            int am = idx >> 2;
            int ak = (idx & 3) << 2;
            float4 av = *(const float4*)(A + (long)(m0 + am) * Kd + k0 + ak);
            As[ak + 0][am] = av.x; As[ak + 1][am] = av.y;
            As[ak + 2][am] = av.z; As[ak + 3][am] = av.w;
            // B: 16 rows x 128 cols
            int bk = idx >> 5;
            int bn = (idx & 31) << 2;
            *(float4*)&Bs[bk][bn] =
                *(const float4*)(Bm + (long)(k0 + bk) * N + n0 + bn);
        }
        __syncthreads();
        #pragma unroll
        for (int kk = 0; kk < 16; kk++) {
            float af[8], bf[8];
            #pragma unroll
            for (int i = 0; i < 8; i++) af[i] = As[kk][trow + i];
            #pragma unroll
            for (int j = 0; j < 8; j++) bf[j] = Bs[kk][tcol + j];
            #pragma unroll
            for (int i = 0; i < 8; i++)
                #pragma unroll
                for (int j = 0; j < 8; j++) acc[i][j] += af[i] * bf[j];
        }
        __syncthreads();
    }
    #pragma unroll
    for (int i = 0; i < 8; i++)
        #pragma unroll
        for (int j = 0; j < 8; j += 4) {
            float4 v = make_float4(acc[i][j], acc[i][j+1], acc[i][j+2], acc[i][j+3]);
            *(float4*)(C + (long)(m0 + trow + i) * N + n0 + tcol + j) = v;
        }
}

// ---------------- small projections: braw = x@Wb, araw = x@Wa (N=8 each) ----------------
__global__ __launch_bounds__(512) void ba_kernel(
    const float* __restrict__ x, const float* __restrict__ Wb,
    const float* __restrict__ Wa)
{
    long m = blockIdx.x;            // row 0..8191
    int tid = threadIdx.x, warp = tid >> 5, lane = tid & 31;
    __shared__ float xs[Dd];
    for (int i = tid; i < Dd; i += 512) xs[i] = x[m * Dd + i];
    __syncthreads();
    const float* W = (warp < 8) ? Wb : Wa;
    int col = warp & 7;
    float acc = 0.f;
    for (int i = lane; i < Dd; i += 32) acc += xs[i] * W[i * Hh + col];
    #pragma unroll
    for (int off = 16; off; off >>= 1) acc += __shfl_xor_sync(0xffffffffu, acc, off);
    if (lane == 0) {
        if (warp < 8) g_braw[m * Hh + col] = acc;
        else          g_araw[m * Hh + col] = acc;
    }
}

// ---------------- causal dwconv(4) + SiLU + per-head l2norm (for q, k) ----------------
__global__ __launch_bounds__(128) void convqk_kernel(
    const float* __restrict__ proj, const float* __restrict__ w,
    float* __restrict__ out, float scale)
{
    int c = threadIdx.x;            // 0..127 within head
    int h = blockIdx.y;             // 0..7
    long bt = blockIdx.x;           // 0..8191
    int t = (int)(bt & (Tt - 1));
    int ch = h * Kk + c;
    long base = bt * HK + ch;
    float y = 0.f;
    #pragma unroll
    for (int i = 0; i < 4; i++) {
        int tt = t - 3 + i;
        if (tt >= 0) y += w[ch * 4 + i] * proj[base + (long)(i - 3) * HK];
    }
    y = y / (1.f + expf(-y));       // SiLU
    float ss = y * y;
    #pragma unroll
    for (int off = 16; off; off >>= 1) ss += __shfl_xor_sync(0xffffffffu, ss, off);
    __shared__ float sred[4];
    if ((c & 31) == 0) sred[c >> 5] = ss;
    __syncthreads();
    float tot = sred[0] + sred[1] + sred[2] + sred[3];
    out[base] = y * rsqrtf(tot + 1e-6f) * scale;
}

// ---------------- causal dwconv(4) + SiLU for v (no norm) ----------------
__global__ __launch_bounds__(256) void convv_kernel(
    const float* __restrict__ proj, const float* __restrict__ w)
{
    long idx = (long)blockIdx.x * blockDim.x + threadIdx.x;
    if (idx >= (long)BT * HV) return;
    int c = (int)(idx & (HV - 1));
    long bt = idx >> 11;
    int t = (int)(bt & (Tt - 1));
    float y = 0.f;
    #pragma unroll
    for (int i = 0; i < 4; i++) {
        int tt = t - 3 + i;
        if (tt >= 0) y += w[c * 4 + i] * proj[idx + (long)(i - 3) * HV];
    }
    g_vn[idx] = y / (1.f + expf(-y));
}

// ---------------- beta = sigmoid(braw); g = -exp(A_log)*softplus(araw + dt_bias) ----------------
__global__ __launch_bounds__(256) void bg_kernel(
    const float* __restrict__ A_log, const float* __restrict__ dt_bias)
{
    int i = blockIdx.x * blockDim.x + threadIdx.x;
    if (i >= BT * Hh) return;
    int h = i & (Hh - 1);
    g_beta[i] = 1.f / (1.f + expf(-g_braw[i]));
    float a = g_araw[i] + dt_bias[h];
    float sp = (a > 20.f) ? a : log1pf(expf(a));
    g_gd[i] = -expf(A_log[h]) * sp;
}

// ---------------- gated delta-rule scan: one warp per (b,h,v-column) ----------------
// State column S[:,col] (K=128 floats) lives in registers: float4 per lane.
__global__ __launch_bounds__(256) void scan_kernel()
{
    const int warp = (blockIdx.x * blockDim.x + threadIdx.x) >> 5;
    const int lane = threadIdx.x & 31;
    const int col  = warp & (Vv - 1);
    const int bh   = warp >> 8;        // 0..15
    const int h    = bh & (Hh - 1);
    const int b    = bh >> 3;

    const float* qp = g_qn + (long)b * Tt * HK + h * Kk + lane * 4;
    const float* kp = g_kn + (long)b * Tt * HK + h * Kk + lane * 4;
    const float* vp = g_vn + (long)b * Tt * HV + h * Vv + col;
    const float* gp = g_gd + (long)b * Tt * Hh + h;
    const float* bp = g_beta + (long)b * Tt * Hh + h;
    float*       op = g_o  + (long)b * Tt * HV + h * Vv + col;

    float4 S = make_float4(0.f, 0.f, 0.f, 0.f);

    // prefetch t=0
    float4 kvN = *(const float4*)kp;
    float4 qvN = *(const float4*)qp;
    float gN = *gp, btN = *bp, vN = *vp;

    for (int t = 0; t < Tt; t++) {
        float4 kv = kvN, qv = qvN;
        float gt = gN, btv = btN, vt = vN;
        if (t + 1 < Tt) {   // prefetch next step (independent of state chain)
            kvN = *(const float4*)(kp + (t + 1) * HK);
            qvN = *(const float4*)(qp + (t + 1) * HK);
            gN  = gp[(t + 1) * Hh];
            btN = bp[(t + 1) * Hh];
            vN  = vp[(t + 1) * HV];
        }
        float d = __expf(gt);
        S.x *= d; S.y *= d; S.z *= d; S.w *= d;
        // r = k . S(:,col)
        float r = kv.x * S.x + kv.y * S.y + kv.z * S.z + kv.w * S.w;
        #pragma unroll
        for (int off = 16; off; off >>= 1) r += __shfl_xor_sync(0xffffffffu, r, off);
        float vnew = btv * (vt - r);
        S.x += kv.x * vnew; S.y += kv.y * vnew;
        S.z += kv.z * vnew; S.w += kv.w * vnew;
        // o = q . S(:,col)
        float ro = qv.x * S.x + qv.y * S.y + qv.z * S.z + qv.w * S.w;
        #pragma unroll
        for (int off = 16; off; off >>= 1) ro += __shfl_xor_sync(0xffffffffu, ro, off);
        if (lane == 0) op[(long)t * HV] = ro;
    }
}

// ---------------- per-head RMSNorm over V=256 ----------------
__global__ __launch_bounds__(256) void rmsnorm_kernel(const float* __restrict__ nw)
{
    long r = blockIdx.x;            // 0..B*T*H-1
    int c = threadIdx.x;            // 0..255
    float v = g_o[r * Vv + c];
    float ss = v * v;
    #pragma unroll
    for (int off = 16; off; off >>= 1) ss += __shfl_xor_sync(0xffffffffu, ss, off);
    __shared__ float sred[8];
    if ((c & 31) == 0) sred[c >> 5] = ss;
    __syncthreads();
    float tot = 0.f;
    #pragma unroll
    for (int j = 0; j < 8; j++) tot += sred[j];
    float ms = tot * (1.f / (float)Vv);
    g_on[r * Vv + c] = v * rsqrtf(ms + 1e-5f) * nw[c];
}

// ---------------- host launcher ----------------
static float* sym_addr(const void* symbol)
{
    void* p = nullptr;
    cudaGetSymbolAddress(&p, symbol);
    return (float*)p;
}

extern "C" void kernel_launch(void* const* d_in, const int* in_sizes, int n_in,
                              void* d_out, int out_size)
{
    const float* x       = (const float*)d_in[0];
    const float* Wq      = (const float*)d_in[1];
    const float* Wk      = (const float*)d_in[2];
    const float* Wv      = (const float*)d_in[3];
    const float* Wb      = (const float*)d_in[4];
    const float* Wa      = (const float*)d_in[5];
    const float* A_log   = (const float*)d_in[6];
    const float* dt_bias = (const float*)d_in[7];
    const float* cqw     = (const float*)d_in[8];
    const float* ckw     = (const float*)d_in[9];
    const float* cvw     = (const float*)d_in[10];
    const float* norm_w  = (const float*)d_in[11];
    const float* Wo      = (const float*)d_in[12];
    float* out           = (float*)d_out;

    float* qproj = sym_addr(g_qproj);
    float* kproj = sym_addr(g_kproj);
    float* vproj = sym_addr(g_vproj);
    float* qn    = sym_addr(g_qn);
    float* kn    = sym_addr(g_kn);
    float* on    = sym_addr(g_on);

    // 1) projections
    sgemm_kernel<<<dim3(HK / 128, BT / 128), 256>>>(x, Wq, qproj, BT, HK, Dd);
    sgemm_kernel<<<dim3(HK / 128, BT / 128), 256>>>(x, Wk, kproj, BT, HK, Dd);
    sgemm_kernel<<<dim3(HV / 128, BT / 128), 256>>>(x, Wv, vproj, BT, HV, Dd);
    ba_kernel<<<BT, 512>>>(x, Wb, Wa);

    // 2) conv + silu (+ l2norm for q,k), beta/g
    convqk_kernel<<<dim3(BT, Hh), 128>>>(qproj, cqw, qn, 0.08838834764831845f); // K^-0.5
    convqk_kernel<<<dim3(BT, Hh), 128>>>(kproj, ckw, kn, 1.0f);
    convv_kernel<<<(BT * HV + 255) / 256, 256>>>(vproj, cvw);
    bg_kernel<<<(BT * Hh + 255) / 256, 256>>>(A_log, dt_bias);

    // 3) gated delta scan: 4096 warps (= B*H*V columns), 8 warps/CTA
    scan_kernel<<<(Bb * Hh * Vv) / 8, 256>>>();

    // 4) per-head RMSNorm, then output projection
    rmsnorm_kernel<<<BT * Hh, 256>>>(norm_w);
    sgemm_kernel<<<dim3(Dd / 128, BT / 128), 256>>>(on, Wo, out, BT, Dd, HV);
}

// round 2
// speedup vs baseline: 1.4396x; 1.4396x over previous
#include <cuda_runtime.h>
#include <cuda_bf16.h>
#include <math.h>

// Problem dims (hardcoded from reference)
#define Bb 2
#define Tt 4096
#define Dd 1024
#define Hh 8
#define Kk 128          // head_k_dim
#define Vv 256          // head_v_dim
#define HK (Hh*Kk)      // 1024
#define HV (Hh*Vv)      // 2048
#define BT (Bb*Tt)      // 8192

// ---------------- scratch (static device globals; no allocation) ----------------
__device__ float g_qproj[BT*HK];
__device__ float g_kproj[BT*HK];
__device__ float g_vproj[BT*HV];
__device__ float g_qn[BT*HK];
__device__ float g_kn[BT*HK];
__device__ float g_vn[BT*HV];
__device__ float g_braw[BT*Hh];
__device__ float g_araw[BT*Hh];
__device__ float g_beta[BT*Hh];
__device__ float g_gd[BT*Hh];
__device__ float g_o[BT*HV];
__device__ float g_on[BT*HV];

// ---------------- helpers ----------------
__device__ __forceinline__ unsigned f2tf(float f) {
    unsigned u;
    asm("cvt.rna.tf32.f32 %0, %1;" : "=r"(u) : "f"(f));
    return u;
}
__device__ __forceinline__ unsigned smem_u32(const void* p) {
    return (unsigned)__cvta_generic_to_shared(p);
}
__device__ __forceinline__ void mma_tf32(float* c, const unsigned* a, const unsigned* b) {
    asm volatile(
        "mma.sync.aligned.m16n8k8.row.col.f32.tf32.tf32.f32 "
        "{%0,%1,%2,%3}, {%4,%5,%6,%7}, {%8,%9}, {%0,%1,%2,%3};"
        : "+f"(c[0]), "+f"(c[1]), "+f"(c[2]), "+f"(c[3])
        : "r"(a[0]), "r"(a[1]), "r"(a[2]), "r"(a[3]), "r"(b[0]), "r"(b[1]));
}
#define CPA16(dst, src) \
    asm volatile("cp.async.cg.shared.global [%0], [%1], 16;\n" :: "r"(dst), "l"(src))

// ---------------- tf32 tensor-core GEMM: C[M,N] = A[M,Kd] * B[Kd,N] ----------------
// 128x128 block tile, BK=16, 256 threads (8 warps, 2x4), warp tile 64x32.
// cp.async double-buffered smem; cvt.rna at fragment load.
__global__ __launch_bounds__(256) void tf32gemm_kernel(
    const float* __restrict__ A, const float* __restrict__ Bm,
    float* __restrict__ C, int M, int N, int Kd)
{
    __shared__ float As[2][128][20];   // BK=16 padded to 20 (conflict-free)
    __shared__ float Bs[2][16][136];   // BN=128 padded to 136 (conflict-free)

    const int tid  = threadIdx.x;
    const int lane = tid & 31;
    const int warp = tid >> 5;
    const int wm   = warp >> 2;        // 0..1 -> m offset wm*64
    const int wn   = warp & 3;         // 0..3 -> n offset wn*32
    const int m0   = blockIdx.y * 128;
    const int n0   = blockIdx.x * 128;

    float acc[4][4][4];
    #pragma unroll
    for (int i = 0; i < 4; i++)
        #pragma unroll
        for (int j = 0; j < 4; j++)
            #pragma unroll
            for (int q = 0; q < 4; q++) acc[i][j][q] = 0.f;

    // stage loader: A tile 128x16 (512 f4), B tile 16x128 (512 f4); 2 f4 each per thread
    auto load_stage = [&](int s, int k0) {
        #pragma unroll
        for (int i = 0; i < 2; i++) {
            int fidx = tid + i * 256;
            int r = fidx >> 2, c = (fidx & 3) << 2;
            CPA16(smem_u32(&As[s][r][c]), A + (long)(m0 + r) * Kd + k0 + c);
        }
        #pragma unroll
        for (int i = 0; i < 2; i++) {
            int fidx = tid + i * 256;
            int r = fidx >> 5, c = (fidx & 31) << 2;
            CPA16(smem_u32(&Bs[s][r][c]), Bm + (long)(k0 + r) * N + n0 + c);
        }
        asm volatile("cp.async.commit_group;");
    };

    const int nIter = Kd >> 4;
    load_stage(0, 0);

    for (int it = 0; it < nIter; ++it) {
        int s = it & 1;
        if (it + 1 < nIter) {
            load_stage(s ^ 1, (it + 1) << 4);
            asm volatile("cp.async.wait_group 1;");
        } else {
            asm volatile("cp.async.wait_group 0;");
        }
        __syncthreads();

        #pragma unroll
        for (int kb = 0; kb < 16; kb += 8) {
            unsigned af[4][4], bf[4][2];
            #pragma unroll
            for (int mt = 0; mt < 4; mt++) {
                int r = wm * 64 + mt * 16 + (lane >> 2);
                int c = kb + (lane & 3);
                af[mt][0] = f2tf(As[s][r][c]);
                af[mt][1] = f2tf(As[s][r + 8][c]);
                af[mt][2] = f2tf(As[s][r][c + 4]);
                af[mt][3] = f2tf(As[s][r + 8][c + 4]);
            }
            #pragma unroll
            for (int nt = 0; nt < 4; nt++) {
                int n = wn * 32 + nt * 8 + (lane >> 2);
                int kk = kb + (lane & 3);
                bf[nt][0] = f2tf(Bs[s][kk][n]);
                bf[nt][1] = f2tf(Bs[s][kk + 4][n]);
            }
            #pragma unroll
            for (int mt = 0; mt < 4; mt++)
                #pragma unroll
                for (int nt = 0; nt < 4; nt++)
                    mma_tf32(acc[mt][nt], af[mt], bf[nt]);
        }
        __syncthreads();
    }

    // store C (c0,c1 contiguous cols; c2,c3 at row+8)
    #pragma unroll
    for (int mt = 0; mt < 4; mt++) {
        int r = m0 + wm * 64 + mt * 16 + (lane >> 2);
        #pragma unroll
        for (int nt = 0; nt < 4; nt++) {
            int cc = n0 + wn * 32 + nt * 8 + ((lane & 3) << 1);
            *(float2*)(C + (long)r * N + cc)       = make_float2(acc[mt][nt][0], acc[mt][nt][1]);
            *(float2*)(C + (long)(r + 8) * N + cc) = make_float2(acc[mt][nt][2], acc[mt][nt][3]);
        }
    }
}

// ---------------- small projections: braw = x@Wb, araw = x@Wa (N=8 each) ----------------
// Block handles 64 rows; W loads are near-uniform per warp (one 32B sector).
__global__ __launch_bounds__(512) void ba_kernel(
    const float* __restrict__ x, const float* __restrict__ Wb,
    const float* __restrict__ Wa)
{
    __shared__ float xs[64][68];
    const int m0  = blockIdx.x * 64;
    const int tid = threadIdx.x;
    const int ml  = tid >> 3;      // 0..63
    const int col = tid & 7;       // 0..7
    float accb = 0.f, acca = 0.f;

    for (int k0 = 0; k0 < Dd; k0 += 64) {
        __syncthreads();
        #pragma unroll
        for (int i = 0; i < 2; i++) {
            int fidx = tid + i * 512;
            int r = fidx >> 4, c = (fidx & 15) << 2;
            *(float4*)&xs[r][c] = *(const float4*)(x + (long)(m0 + r) * Dd + k0 + c);
        }
        __syncthreads();
        #pragma unroll 8
        for (int i = 0; i < 64; i++) {
            float xv = xs[ml][i];
            accb += xv * Wb[(k0 + i) * Hh + col];
            acca += xv * Wa[(k0 + i) * Hh + col];
        }
    }
    g_braw[(long)(m0 + ml) * Hh + col] = accb;
    g_araw[(long)(m0 + ml) * Hh + col] = acca;
}

// ---------------- causal dwconv(4) + SiLU + per-head l2norm (for q, k) ----------------
__global__ __launch_bounds__(128) void convqk_kernel(
    const float* __restrict__ proj, const float* __restrict__ w,
    float* __restrict__ out, float scale)
{
    int c = threadIdx.x;            // 0..127 within head
    int h = blockIdx.y;             // 0..7
    long bt = blockIdx.x;           // 0..8191
    int t = (int)(bt & (Tt - 1));
    int ch = h * Kk + c;
    long base = bt * HK + ch;
    float y = 0.f;
    #pragma unroll
    for (int i = 0; i < 4; i++) {
        int tt = t - 3 + i;
        if (tt >= 0) y += w[ch * 4 + i] * proj[base + (long)(i - 3) * HK];
    }
    y = y / (1.f + expf(-y));       // SiLU
    float ss = y * y;
    #pragma unroll
    for (int off = 16; off; off >>= 1) ss += __shfl_xor_sync(0xffffffffu, ss, off);
    __shared__ float sred[4];
    if ((c & 31) == 0) sred[c >> 5] = ss;
    __syncthreads();
    float tot = sred[0] + sred[1] + sred[2] + sred[3];
    out[base] = y * rsqrtf(tot + 1e-6f) * scale;
}

// ---------------- causal dwconv(4) + SiLU for v (no norm) ----------------
__global__ __launch_bounds__(256) void convv_kernel(
    const float* __restrict__ proj, const float* __restrict__ w)
{
    long idx = (long)blockIdx.x * blockDim.x + threadIdx.x;
    if (idx >= (long)BT * HV) return;
    int c = (int)(idx & (HV - 1));
    long bt = idx >> 11;
    int t = (int)(bt & (Tt - 1));
    float y = 0.f;
    #pragma unroll
    for (int i = 0; i < 4; i++) {
        int tt = t - 3 + i;
        if (tt >= 0) y += w[c * 4 + i] * proj[idx + (long)(i - 3) * HV];
    }
    g_vn[idx] = y / (1.f + expf(-y));
}

// ---------------- beta = sigmoid(braw); g = -exp(A_log)*softplus(araw + dt_bias) ----------------
__global__ __launch_bounds__(256) void bg_kernel(
    const float* __restrict__ A_log, const float* __restrict__ dt_bias)
{
    int i = blockIdx.x * blockDim.x + threadIdx.x;
    if (i >= BT * Hh) return;
    int h = i & (Hh - 1);
    g_beta[i] = 1.f / (1.f + expf(-g_braw[i]));
    float a = g_araw[i] + dt_bias[h];
    float sp = (a > 20.f) ? a : log1pf(expf(a));
    g_gd[i] = -expf(A_log[h]) * sp;
}

// ---------------- gated delta-rule scan: one warp per (b,h,v-column) ----------------
// State column S[:,col] (K=128 floats) lives in registers: float4 per lane.
__global__ __launch_bounds__(256) void scan_kernel()
{
    const int warp = (blockIdx.x * blockDim.x + threadIdx.x) >> 5;
    const int lane = threadIdx.x & 31;
    const int col  = warp & (Vv - 1);
    const int bh   = warp >> 8;        // 0..15
    const int h    = bh & (Hh - 1);
    const int b    = bh >> 3;

    const float* qp = g_qn + (long)b * Tt * HK + h * Kk + lane * 4;
    const float* kp = g_kn + (long)b * Tt * HK + h * Kk + lane * 4;
    const float* vp = g_vn + (long)b * Tt * HV + h * Vv + col;
    const float* gp = g_gd + (long)b * Tt * Hh + h;
    const float* bp = g_beta + (long)b * Tt * Hh + h;
    float*       op = g_o  + (long)b * Tt * HV + h * Vv + col;

    float4 S = make_float4(0.f, 0.f, 0.f, 0.f);

    // prefetch t=0
    float4 kvN = *(const float4*)kp;
    float4 qvN = *(const float4*)qp;
    float gN = *gp, btN = *bp, vN = *vp;

    for (int t = 0; t < Tt; t++) {
        float4 kv = kvN, qv = qvN;
        float gt = gN, btv = btN, vt = vN;
        if (t + 1 < Tt) {   // prefetch next step (independent of state chain)
            kvN = *(const float4*)(kp + (t + 1) * HK);
            qvN = *(const float4*)(qp + (t + 1) * HK);
            gN  = gp[(t + 1) * Hh];
            btN = bp[(t + 1) * Hh];
            vN  = vp[(t + 1) * HV];
        }
        float d = __expf(gt);
        S.x *= d; S.y *= d; S.z *= d; S.w *= d;
        // r = k . S(:,col)
        float r = kv.x * S.x + kv.y * S.y + kv.z * S.z + kv.w * S.w;
        #pragma unroll
        for (int off = 16; off; off >>= 1) r += __shfl_xor_sync(0xffffffffu, r, off);
        float vnew = btv * (vt - r);
        S.x += kv.x * vnew; S.y += kv.y * vnew;
        S.z += kv.z * vnew; S.w += kv.w * vnew;
        // o = q . S(:,col)
        float ro = qv.x * S.x + qv.y * S.y + qv.z * S.z + qv.w * S.w;
        #pragma unroll
        for (int off = 16; off; off >>= 1) ro += __shfl_xor_sync(0xffffffffu, ro, off);
        if (lane == 0) op[(long)t * HV] = ro;
    }
}

// ---------------- per-head RMSNorm over V=256 ----------------
__global__ __launch_bounds__(256) void rmsnorm_kernel(const float* __restrict__ nw)
{
    long r = blockIdx.x;            // 0..B*T*H-1
    int c = threadIdx.x;            // 0..255
    float v = g_o[r * Vv + c];
    float ss = v * v;
    #pragma unroll
    for (int off = 16; off; off >>= 1) ss += __shfl_xor_sync(0xffffffffu, ss, off);
    __shared__ float sred[8];
    if ((c & 31) == 0) sred[c >> 5] = ss;
    __syncthreads();
    float tot = 0.f;
    #pragma unroll
    for (int j = 0; j < 8; j++) tot += sred[j];
    float ms = tot * (1.f / (float)Vv);
    g_on[r * Vv + c] = v * rsqrtf(ms + 1e-5f) * nw[c];
}

// ---------------- host launcher ----------------
static float* sym_addr(const void* symbol)
{
    void* p = nullptr;
    cudaGetSymbolAddress(&p, symbol);
    return (float*)p;
}

extern "C" void kernel_launch(void* const* d_in, const int* in_sizes, int n_in,
                              void* d_out, int out_size)
{
    const float* x       = (const float*)d_in[0];
    const float* Wq      = (const float*)d_in[1];
    const float* Wk      = (const float*)d_in[2];
    const float* Wv      = (const float*)d_in[3];
    const float* Wb      = (const float*)d_in[4];
    const float* Wa      = (const float*)d_in[5];
    const float* A_log   = (const float*)d_in[6];
    const float* dt_bias = (const float*)d_in[7];
    const float* cqw     = (const float*)d_in[8];
    const float* ckw     = (const float*)d_in[9];
    const float* cvw     = (const float*)d_in[10];
    const float* norm_w  = (const float*)d_in[11];
    const float* Wo      = (const float*)d_in[12];
    float* out           = (float*)d_out;

    float* qproj = sym_addr(g_qproj);
    float* kproj = sym_addr(g_kproj);
    float* vproj = sym_addr(g_vproj);
    float* qn    = sym_addr(g_qn);
    float* kn    = sym_addr(g_kn);
    float* on    = sym_addr(g_on);

    // 1) projections (tf32 tensor cores)
    tf32gemm_kernel<<<dim3(HK / 128, BT / 128), 256>>>(x, Wq, qproj, BT, HK, Dd);
    tf32gemm_kernel<<<dim3(HK / 128, BT / 128), 256>>>(x, Wk, kproj, BT, HK, Dd);
    tf32gemm_kernel<<<dim3(HV / 128, BT / 128), 256>>>(x, Wv, vproj, BT, HV, Dd);
    ba_kernel<<<BT / 64, 512>>>(x, Wb, Wa);

    // 2) conv + silu (+ l2norm for q,k), beta/g
    convqk_kernel<<<dim3(BT, Hh), 128>>>(qproj, cqw, qn, 0.08838834764831845f); // K^-0.5
    convqk_kernel<<<dim3(BT, Hh), 128>>>(kproj, ckw, kn, 1.0f);
    convv_kernel<<<(BT * HV + 255) / 256, 256>>>(vproj, cvw);
    bg_kernel<<<(BT * Hh + 255) / 256, 256>>>(A_log, dt_bias);

    // 3) gated delta scan: 4096 warps (= B*H*V columns), 8 warps/CTA
    scan_kernel<<<(Bb * Hh * Vv) / 8, 256>>>();

    // 4) per-head RMSNorm, then output projection (tf32 tensor cores)
    rmsnorm_kernel<<<BT * Hh, 256>>>(norm_w);
    tf32gemm_kernel<<<dim3(Dd / 128, BT / 128), 256>>>(on, Wo, out, BT, Dd, HV);
}